// round 15
// baseline (speedup 1.0000x reference)
#include <cuda_runtime.h>
#include <cuda_bf16.h>
#include <cuda_fp16.h>
#include <cstdint>

// Problem constants: N=50000, E=800000, dims 64/128/2.
#define MAXN 50176                     // 392 * 128, padded
#define MAXE 800000
#define NSPLIT 25088                   // 196 * 128, row-block pipeline split

// -------- device scratch (no allocations allowed) --------
__device__ __half g_xw0[MAXN * 128];   // conv GEMM output plane 0 (fp16)
__device__ __half g_xw1[MAXN * 128];   // conv GEMM output plane 1 (fp16)
__device__ __half g_H[MAXN * 384];     // concat hidden (fp16)
__device__ __half g_x16[MAXN * 64];    // x in fp16
__device__ float  g_out2[MAXN * 2];    // fused MLP partial sums
__device__ __half g_W1h[128 * 64],  g_W1l[128 * 64];    // [out][in] fp16 hi/lo
__device__ __half g_W2h[128 * 128], g_W2l[128 * 128];
__device__ __half g_W3h[128 * 128], g_W3l[128 * 128];
__device__ __half g_L1h[384 * 384], g_L1l[384 * 384];   // lW1 already [out][in]
__device__ int   g_deg[MAXN];
__device__ float g_dinv[MAXN];
__device__ int   g_rp[MAXN + 1];
__device__ int   g_cur[MAXN];
__device__ int   g_col[MAXE];
__device__ float g_wf[MAXE];           // dinv[src]*dinv[dst] per CSR slot
__device__ int   g_bsums[64];

// ======================= helpers =======================

__device__ __forceinline__ uint32_t s2u(const void* p) {
    uint32_t a;
    asm("{ .reg .u64 t; cvta.to.shared.u64 t, %1; cvt.u32.u64 %0, t; }" : "=r"(a) : "l"(p));
    return a;
}

__device__ __forceinline__ void cpa16(uint32_t sdst, const void* gsrc) {
    asm volatile("cp.async.cg.shared.global [%0], [%1], 16;" :: "r"(sdst), "l"(gsrc) : "memory");
}
__device__ __forceinline__ void cpa_commit() {
    asm volatile("cp.async.commit_group;" ::: "memory");
}
template <int N>
__device__ __forceinline__ void cpa_wait() {
    asm volatile("cp.async.wait_group %0;" :: "n"(N) : "memory");
}

__device__ __forceinline__ void ldsm4(uint32_t& r0, uint32_t& r1, uint32_t& r2, uint32_t& r3,
                                      uint32_t addr) {
    asm volatile("ldmatrix.sync.aligned.m8n8.x4.shared.b16 {%0,%1,%2,%3}, [%4];"
                 : "=r"(r0), "=r"(r1), "=r"(r2), "=r"(r3) : "r"(addr));
}

__device__ __forceinline__ void mma_h(float* c, uint32_t a0, uint32_t a1, uint32_t a2,
                                      uint32_t a3, uint32_t b0, uint32_t b1) {
    asm volatile(
        "mma.sync.aligned.m16n8k16.row.col.f32.f16.f16.f32 "
        "{%0,%1,%2,%3}, {%4,%5,%6,%7}, {%8,%9}, {%0,%1,%2,%3};"
        : "+f"(c[0]), "+f"(c[1]), "+f"(c[2]), "+f"(c[3])
        : "r"(a0), "r"(a1), "r"(a2), "r"(a3), "r"(b0), "r"(b1));
}

__device__ __forceinline__ void wsplit(float x, __half& h, __half& l) {
    h = __float2half_rn(x);
    l = __float2half_rn(x - __half2float(h));
}

// ======================= graph preprocessing =======================

__global__ void k_zero(int n) {
    int i = blockIdx.x * blockDim.x + threadIdx.x;
    if (i < n) g_deg[i] = 0;
}
__global__ void k_deg(const int* __restrict__ dst, int e) {
    int i = blockIdx.x * blockDim.x + threadIdx.x;
    if (i < e) atomicAdd(&g_deg[dst[i]], 1);
}
__global__ void k_scan1(int n) {
    __shared__ int sh[1024];
    int i = blockIdx.x * 1024 + threadIdx.x;
    int v = (i < n) ? g_deg[i] : 0;
    if (i < n) g_dinv[i] = rsqrtf((float)(v + 1));   // fused dinv
    sh[threadIdx.x] = v;
    __syncthreads();
    for (int o = 1; o < 1024; o <<= 1) {
        int t = (threadIdx.x >= o) ? sh[threadIdx.x - o] : 0;
        __syncthreads();
        sh[threadIdx.x] += t;
        __syncthreads();
    }
    int incl = sh[threadIdx.x];
    if (i < n) g_rp[i] = incl - v;
    if (threadIdx.x == 1023) g_bsums[blockIdx.x] = incl;
}
// scan3 with scan2 folded in: every block redundantly exclusive-scans bsums.
__global__ void k_scan3(int n, int e, int nb) {
    __shared__ int sh[64];
    if (threadIdx.x < 64) sh[threadIdx.x] = (threadIdx.x < nb) ? g_bsums[threadIdx.x] : 0;
    __syncthreads();
    if (threadIdx.x == 0) {
        int run = 0;
        for (int b = 0; b < 64; ++b) { int t = sh[b]; sh[b] = run; run += t; }
    }
    __syncthreads();
    int i = blockIdx.x * 1024 + threadIdx.x;
    if (i < n) {
        int v = g_rp[i] + sh[blockIdx.x];
        g_rp[i] = v;
        g_cur[i] = v;
    }
    if (i == 0) g_rp[n] = e;
}
__global__ void k_fill(const int* __restrict__ src, const int* __restrict__ dst, int e) {
    int i = blockIdx.x * blockDim.x + threadIdx.x;
    if (i < e) {
        int s = src[i], d = dst[i];
        int p = atomicAdd(&g_cur[d], 1);
        g_col[p] = s;
        g_wf[p] = g_dinv[s] * g_dinv[d];
    }
}

// ======================= pre-conversion =======================

__global__ void k_cvt_x(const float* __restrict__ x, int n) {
    int i = blockIdx.x * blockDim.x + threadIdx.x;     // float4 groups: MAXN*16
    if (i >= MAXN * 16) return;
    int row = i >> 4;
    int c4 = (i & 15) << 2;
    float4 v = make_float4(0.f, 0.f, 0.f, 0.f);
    if (row < n) v = *(const float4*)(x + (size_t)row * 64 + c4);
    size_t o = (size_t)row * 64 + c4;
    *(__half2*)(g_x16 + o)     = __floats2half2_rn(v.x, v.y);
    *(__half2*)(g_x16 + o + 2) = __floats2half2_rn(v.z, v.w);
    if ((i & 15) == 0) {                // one thread per row zeroes g_out2
        g_out2[2 * row] = 0.f;
        g_out2[2 * row + 1] = 0.f;
    }
}

__global__ void k_cvt_w(const float* __restrict__ W1, const float* __restrict__ W2,
                        const float* __restrict__ W3, const float* __restrict__ L1) {
    int i = blockIdx.x * blockDim.x + threadIdx.x;
    if (i < 8192) {                      // W1: [64][128] -> [128][64]
        int o = i / 64, k = i % 64;
        wsplit(W1[(size_t)k * 128 + o], g_W1h[i], g_W1l[i]);
    } else if (i < 24576) {              // W2: [128][128] -> T
        int j = i - 8192;
        int o = j / 128, k = j % 128;
        wsplit(W2[(size_t)k * 128 + o], g_W2h[j], g_W2l[j]);
    } else if (i < 40960) {              // W3
        int j = i - 24576;
        int o = j / 128, k = j % 128;
        wsplit(W3[(size_t)k * 128 + o], g_W3h[j], g_W3l[j]);
    } else if (i < 188416) {             // lW1 straight copy-split
        int j = i - 40960;
        wsplit(L1[j], g_L1h[j], g_L1l[j]);
    }
}

// ======= fp16 GEMM: A single plane, B hi/lo (2-term), 3-stage pipeline ======
// BM=128, BN=128. m0 = row offset for row-block pipelining.
// EPI==0: fp16 store. EPI==2: fused MLP tail -> g_out2.

#define PITCH 80
#define PLANE (128 * PITCH)            // 10240
#define STG (3 * PLANE)                // 30720
#define SM_TOTAL (3 * STG)             // 92160

template <int EPI>
__global__ __launch_bounds__(256, 2)
void mm3(const __half* __restrict__ A, int lda,
         const __half* __restrict__ Bh, const __half* __restrict__ Bl, int ldb,
         __half* __restrict__ C, int ldc, const float* __restrict__ bias,
         const float* __restrict__ w2, int K, int m0)
{
    extern __shared__ char smem[];
    uint32_t sb = s2u(smem);
    int tid = threadIdx.x;
    int lane = tid & 31;
    int wid = tid >> 5;
    int warp_m = wid & 3;
    int warp_n = wid >> 2;

    int bm = m0 + blockIdx.x * 128;
    int bn = blockIdx.y * 128;

    float acc[2][8][4];
#pragma unroll
    for (int a = 0; a < 2; ++a)
#pragma unroll
        for (int b = 0; b < 8; ++b)
#pragma unroll
            for (int c = 0; c < 4; ++c) acc[a][b][c] = 0.f;

    int a_r = (lane & 7) + ((lane & 8) ? 8 : 0);
    int a_c8 = (lane & 16) ? 8 : 0;
    int b_r = (lane & 7) + ((lane & 16) ? 8 : 0);
    int b_c8 = (lane & 8) ? 8 : 0;

    int nch = K >> 5;      // 32-wide K chunks

    auto issue = [&](int ch) {
        int k0 = ch << 5;
        uint32_t base = sb + (ch % 3) * STG;
#pragma unroll
        for (int t = tid; t < 512; t += 256) {
            int row = t >> 2;
            int c = (t & 3) << 4;                  // 0,16,32,48 bytes
            uint32_t d = base + row * PITCH + c;
            cpa16(d,             (const char*)(A  + (size_t)(bm + row) * lda + k0) + c);
            cpa16(d + PLANE,     (const char*)(Bh + (size_t)(bn + row) * ldb + k0) + c);
            cpa16(d + 2 * PLANE, (const char*)(Bl + (size_t)(bn + row) * ldb + k0) + c);
        }
        cpa_commit();
    };

    issue(0);
    if (nch > 1) issue(1);
    for (int ch = 0; ch < nch; ++ch) {
        if (ch + 2 < nch) {
            issue(ch + 2);
            cpa_wait<2>();
        } else if (ch + 1 < nch) {
            cpa_wait<1>();
        } else {
            cpa_wait<0>();
        }
        __syncthreads();

        uint32_t pA  = sb + (ch % 3) * STG;
        uint32_t pBH = pA + PLANE;
        uint32_t pBL = pA + 2 * PLANE;

#pragma unroll
        for (int k16 = 0; k16 < 2; ++k16) {
            int kb = k16 * 16;
            uint32_t ah[2][4];
#pragma unroll
            for (int mt = 0; mt < 2; ++mt) {
                int rr = warp_m * 32 + mt * 16 + a_r;
                uint32_t off = (uint32_t)(rr * PITCH + (kb + a_c8) * 2);
                ldsm4(ah[mt][0], ah[mt][1], ah[mt][2], ah[mt][3], pA + off);
            }
#pragma unroll
            for (int half = 0; half < 2; ++half) {
                uint32_t bh[4][2], bl[4][2];
#pragma unroll
                for (int pair = 0; pair < 2; ++pair) {
                    int nn = warp_n * 64 + half * 32 + pair * 16 + b_r;
                    uint32_t off = (uint32_t)(nn * PITCH + (kb + b_c8) * 2);
                    ldsm4(bh[pair * 2][0], bh[pair * 2][1],
                          bh[pair * 2 + 1][0], bh[pair * 2 + 1][1], pBH + off);
                    ldsm4(bl[pair * 2][0], bl[pair * 2][1],
                          bl[pair * 2 + 1][0], bl[pair * 2 + 1][1], pBL + off);
                }
#pragma unroll
                for (int mt = 0; mt < 2; ++mt) {
#pragma unroll
                    for (int nt = 0; nt < 4; ++nt) {
                        float* c = acc[mt][half * 4 + nt];
                        mma_h(c, ah[mt][0], ah[mt][1], ah[mt][2], ah[mt][3],
                              bh[nt][0], bh[nt][1]);
                        mma_h(c, ah[mt][0], ah[mt][1], ah[mt][2], ah[mt][3],
                              bl[nt][0], bl[nt][1]);
                    }
                }
            }
        }
        __syncthreads();
    }

    int gid = lane >> 2;
    int tig = lane & 3;

    if (EPI == 2) {
        float p[2][2][2] = {};                      // [mt][row half][out]
#pragma unroll
        for (int g = 0; g < 8; ++g) {
            int col = bn + warp_n * 64 + g * 8 + tig * 2;
            float bb0 = __ldg(bias + col), bb1 = __ldg(bias + col + 1);
            float w00 = __ldg(w2 + col),       w01 = __ldg(w2 + col + 1);
            float w10 = __ldg(w2 + 384 + col), w11 = __ldg(w2 + 385 + col);
#pragma unroll
            for (int mt = 0; mt < 2; ++mt) {
                float* c = acc[mt][g];
                float v0 = fmaxf(c[0] + bb0, 0.f);
                float v1 = fmaxf(c[1] + bb1, 0.f);
                float v2 = fmaxf(c[2] + bb0, 0.f);
                float v3 = fmaxf(c[3] + bb1, 0.f);
                p[mt][0][0] += v0 * w00 + v1 * w01;
                p[mt][0][1] += v0 * w10 + v1 * w11;
                p[mt][1][0] += v2 * w00 + v3 * w01;
                p[mt][1][1] += v2 * w10 + v3 * w11;
            }
        }
#pragma unroll
        for (int mt = 0; mt < 2; ++mt)
#pragma unroll
            for (int r = 0; r < 2; ++r)
#pragma unroll
                for (int o = 0; o < 2; ++o) {
                    float v = p[mt][r][o];
                    v += __shfl_xor_sync(0xFFFFFFFFu, v, 1);
                    v += __shfl_xor_sync(0xFFFFFFFFu, v, 2);
                    p[mt][r][o] = v;
                }
        if (tig == 0) {
#pragma unroll
            for (int mt = 0; mt < 2; ++mt) {
                int row0 = bm + warp_m * 32 + mt * 16 + gid;
                atomicAdd(&g_out2[2 * row0 + 0], p[mt][0][0]);
                atomicAdd(&g_out2[2 * row0 + 1], p[mt][0][1]);
                atomicAdd(&g_out2[2 * (row0 + 8) + 0], p[mt][1][0]);
                atomicAdd(&g_out2[2 * (row0 + 8) + 1], p[mt][1][1]);
            }
        }
        return;
    }

#pragma unroll
    for (int mt = 0; mt < 2; ++mt) {
        int row0 = bm + warp_m * 32 + mt * 16 + gid;
#pragma unroll
        for (int g = 0; g < 8; ++g) {
            int col = bn + warp_n * 64 + g * 8 + tig * 2;
            float* c = acc[mt][g];
            *(__half2*)(C + (size_t)row0 * ldc + col)       = __floats2half2_rn(c[0], c[1]);
            *(__half2*)(C + (size_t)(row0 + 8) * ldc + col) = __floats2half2_rn(c[2], c[3]);
        }
    }
}

// ======================= edge aggregation (fp16 gather -> fp16 H) ===========
// node range [base, nlim); gathers from the given xw plane

__global__ void k_agg(const __half* __restrict__ xw, const float* __restrict__ bias,
                      int off, int base, int nlim)
{
    int warp = base + ((blockIdx.x * blockDim.x + threadIdx.x) >> 5);
    int lane = threadIdx.x & 31;
    if (warp >= nlim) return;
    const uint2* xw2 = (const uint2*)xw;        // 32 uint2 per row

    float di = g_dinv[warp];
    float w0 = di * di;
    uint2 ra = xw2[(size_t)warp * 32 + lane];
    float2 a0 = __half22float2(*(__half2*)&ra.x);
    float2 a1 = __half22float2(*(__half2*)&ra.y);
    float s0f = w0 * a0.x, s1f = w0 * a0.y, s2f = w0 * a1.x, s3f = w0 * a1.y;

    int s0 = g_rp[warp], s1 = g_rp[warp + 1];
    int j = s0;
    for (; j + 3 < s1; j += 4) {
        int i0 = g_col[j], i1 = g_col[j + 1], i2 = g_col[j + 2], i3 = g_col[j + 3];
        float u0 = g_wf[j], u1 = g_wf[j + 1], u2 = g_wf[j + 2], u3 = g_wf[j + 3];
        uint2 r0 = xw2[(size_t)i0 * 32 + lane];
        uint2 r1 = xw2[(size_t)i1 * 32 + lane];
        uint2 r2 = xw2[(size_t)i2 * 32 + lane];
        uint2 r3 = xw2[(size_t)i3 * 32 + lane];
        float2 p;
        p = __half22float2(*(__half2*)&r0.x); s0f += u0 * p.x; s1f += u0 * p.y;
        p = __half22float2(*(__half2*)&r0.y); s2f += u0 * p.x; s3f += u0 * p.y;
        p = __half22float2(*(__half2*)&r1.x); s0f += u1 * p.x; s1f += u1 * p.y;
        p = __half22float2(*(__half2*)&r1.y); s2f += u1 * p.x; s3f += u1 * p.y;
        p = __half22float2(*(__half2*)&r2.x); s0f += u2 * p.x; s1f += u2 * p.y;
        p = __half22float2(*(__half2*)&r2.y); s2f += u2 * p.x; s3f += u2 * p.y;
        p = __half22float2(*(__half2*)&r3.x); s0f += u3 * p.x; s1f += u3 * p.y;
        p = __half22float2(*(__half2*)&r3.y); s2f += u3 * p.x; s3f += u3 * p.y;
    }
    for (; j < s1; ++j) {
        int s = g_col[j];
        float w = g_wf[j];
        uint2 r = xw2[(size_t)s * 32 + lane];
        float2 p;
        p = __half22float2(*(__half2*)&r.x); s0f += w * p.x; s1f += w * p.y;
        p = __half22float2(*(__half2*)&r.y); s2f += w * p.x; s3f += w * p.y;
    }
    const float4 b4 = ((const float4*)bias)[lane];
    s0f += b4.x; s1f += b4.y; s2f += b4.z; s3f += b4.w;

    size_t o = (size_t)warp * 384 + off + lane * 4;
    *(__half2*)(g_H + o)     = __floats2half2_rn(s0f, s1f);
    *(__half2*)(g_H + o + 2) = __floats2half2_rn(s2f, s3f);
}

// ======================= final: bias + softmax from fused partials ==========

__global__ void k_final2(const float* __restrict__ lb2, float* __restrict__ out, int n)
{
    int i = blockIdx.x * blockDim.x + threadIdx.x;
    if (i >= n) return;
    float a0 = g_out2[2 * i] + lb2[0];
    float a1 = g_out2[2 * i + 1] + lb2[1];
    out[2 * i] = a0;
    out[2 * i + 1] = a1;
    float m = fmaxf(a0, a1);
    float e0 = expf(a0 - m), e1 = expf(a1 - m);
    float inv = 1.f / (e0 + e1);
    out[(size_t)2 * n + 2 * i] = e0 * inv;
    out[(size_t)2 * n + 2 * i + 1] = e1 * inv;
}

// ======================= launch =======================

extern "C" void kernel_launch(void* const* d_in, const int* in_sizes, int n_in,
                              void* d_out, int out_size)
{
    const float* x   = (const float*)d_in[0];
    const int*   ei  = (const int*)  d_in[1];
    const float* W1  = (const float*)d_in[2];
    const float* b1  = (const float*)d_in[3];
    const float* W2  = (const float*)d_in[4];
    const float* b2  = (const float*)d_in[5];
    const float* W3  = (const float*)d_in[6];
    const float* b3  = (const float*)d_in[7];
    const float* lW1 = (const float*)d_in[8];
    const float* lb1 = (const float*)d_in[9];
    const float* lW2 = (const float*)d_in[10];
    const float* lb2 = (const float*)d_in[11];
    float* out = (float*)d_out;

    int n = in_sizes[0] / 64;   // 50000
    int e = in_sizes[1] / 2;    // 800000
    const int* src = ei;
    const int* dst = ei + e;

    void *p_xw0, *p_xw1, *p_H, *p_x16;
    void *p_W1h, *p_W1l, *p_W2h, *p_W2l, *p_W3h, *p_W3l, *p_L1h, *p_L1l;
    cudaGetSymbolAddress(&p_xw0, g_xw0);
    cudaGetSymbolAddress(&p_xw1, g_xw1);
    cudaGetSymbolAddress(&p_H,   g_H);
    cudaGetSymbolAddress(&p_x16, g_x16);
    cudaGetSymbolAddress(&p_W1h, g_W1h); cudaGetSymbolAddress(&p_W1l, g_W1l);
    cudaGetSymbolAddress(&p_W2h, g_W2h); cudaGetSymbolAddress(&p_W2l, g_W2l);
    cudaGetSymbolAddress(&p_W3h, g_W3h); cudaGetSymbolAddress(&p_W3l, g_W3l);
    cudaGetSymbolAddress(&p_L1h, g_L1h); cudaGetSymbolAddress(&p_L1l, g_L1l);
    __half* H   = (__half*)p_H;
    __half* xw0 = (__half*)p_xw0;
    __half* xw1 = (__half*)p_xw1;

    cudaFuncSetAttribute(mm3<0>, cudaFuncAttributeMaxDynamicSharedMemorySize, SM_TOTAL);
    cudaFuncSetAttribute(mm3<2>, cudaFuncAttributeMaxDynamicSharedMemorySize, SM_TOTAL);

    // one-time side stream + events (host resources, not device mem)
    static cudaStream_t s2 = nullptr;
    static cudaEvent_t evFork = nullptr, evJoin = nullptr;
    static cudaEvent_t evA[3], evB[3];
    if (!s2) {
        cudaStreamCreateWithFlags(&s2, cudaStreamNonBlocking);
        cudaEventCreateWithFlags(&evFork, cudaEventDisableTiming);
        cudaEventCreateWithFlags(&evJoin, cudaEventDisableTiming);
        for (int i = 0; i < 3; ++i) {
            cudaEventCreateWithFlags(&evA[i], cudaEventDisableTiming);
            cudaEventCreateWithFlags(&evB[i], cudaEventDisableTiming);
        }
    }

    int nb = (n + 1023) / 1024;
    int gm = MAXN / 128;               // 392
    int gmA = NSPLIT / 128;            // 196
    int gmB = gm - gmA;                // 196
    int aggA = (NSPLIT + 7) / 8;
    int aggB = (n - NSPLIT + 7) / 8;

    // ---- fork: CSR branch on s2, convert+conv1 on main ----
    cudaEventRecord(evFork, 0);
    cudaStreamWaitEvent(s2, evFork, 0);

    k_zero<<<(n + 255) / 256, 256, 0, s2>>>(n);
    k_deg<<<(e + 255) / 256, 256, 0, s2>>>(dst, e);

    k_cvt_x<<<(MAXN * 16 + 255) / 256, 256>>>(x, n);
    k_cvt_w<<<(188416 + 255) / 256, 256>>>(W1, W2, W3, lW1);

    k_scan1<<<nb, 1024, 0, s2>>>(n);
    k_scan3<<<nb, 1024, 0, s2>>>(n, e, nb);
    k_fill<<<(e + 255) / 256, 256, 0, s2>>>(src, dst, e);
    cudaEventRecord(evJoin, s2);

    // conv1 full -> xw0
    mm3<0><<<dim3(gm, 1), 256, SM_TOTAL>>>((__half*)p_x16, 64,
                                           (__half*)p_W1h, (__half*)p_W1l, 64,
                                           xw0, 128, nullptr, nullptr, 64, 0);

    cudaStreamWaitEvent(0, evJoin, 0);

    // ===== layer 1 -> 2 pipelined (agg1 reads xw0; conv2 writes xw1) =====
    k_agg<<<aggA, 256>>>(xw0, b1, 0, 0, NSPLIT);
    cudaEventRecord(evA[0], 0);
    cudaStreamWaitEvent(s2, evA[0], 0);
    mm3<0><<<dim3(gmA, 1), 256, SM_TOTAL, s2>>>(H, 384,
                                                (__half*)p_W2h, (__half*)p_W2l, 128,
                                                xw1, 128, nullptr, nullptr, 128, 0);
    cudaEventRecord(evB[0], s2);
    k_agg<<<aggB, 256>>>(xw0, b1, 0, NSPLIT, n);
    mm3<0><<<dim3(gmB, 1), 256, SM_TOTAL>>>(H, 384,
                                            (__half*)p_W2h, (__half*)p_W2l, 128,
                                            xw1, 128, nullptr, nullptr, 128, NSPLIT);
    cudaStreamWaitEvent(0, evB[0], 0);

    // ===== layer 2 -> 3 pipelined (agg2 reads xw1; conv3 writes xw0) =====
    k_agg<<<aggA, 256>>>(xw1, b2, 128, 0, NSPLIT);
    cudaEventRecord(evA[1], 0);
    cudaStreamWaitEvent(s2, evA[1], 0);
    mm3<0><<<dim3(gmA, 1), 256, SM_TOTAL, s2>>>(H + 128, 384,
                                                (__half*)p_W3h, (__half*)p_W3l, 128,
                                                xw0, 128, nullptr, nullptr, 128, 0);
    cudaEventRecord(evB[1], s2);
    k_agg<<<aggB, 256>>>(xw1, b2, 128, NSPLIT, n);
    mm3<0><<<dim3(gmB, 1), 256, SM_TOTAL>>>(H + 128, 384,
                                            (__half*)p_W3h, (__half*)p_W3l, 128,
                                            xw0, 128, nullptr, nullptr, 128, NSPLIT);
    cudaStreamWaitEvent(0, evB[1], 0);

    // ===== layer 3 -> lW1 pipelined (agg3 reads xw0; lW1 reads H only) =====
    k_agg<<<aggA, 256>>>(xw0, b3, 256, 0, NSPLIT);
    cudaEventRecord(evA[2], 0);
    cudaStreamWaitEvent(s2, evA[2], 0);
    mm3<2><<<dim3(gmA, 3), 256, SM_TOTAL, s2>>>(H, 384,
                                                (__half*)p_L1h, (__half*)p_L1l, 384,
                                                nullptr, 0, lb1, lW2, 384, 0);
    cudaEventRecord(evB[2], s2);
    k_agg<<<aggB, 256>>>(xw0, b3, 256, NSPLIT, n);
    mm3<2><<<dim3(gmB, 3), 256, SM_TOTAL>>>(H, 384,
                                            (__half*)p_L1h, (__half*)p_L1l, 384,
                                            nullptr, 0, lb1, lW2, 384, NSPLIT);
    cudaStreamWaitEvent(0, evB[2], 0);

    // bias + softmax
    k_final2<<<(n + 255) / 256, 256>>>(lb2, out, n);
}

// round 16
// speedup vs baseline: 1.1753x; 1.1753x over previous
#include <cuda_runtime.h>
#include <cuda_bf16.h>
#include <cuda_fp16.h>
#include <cstdint>

// Problem constants: N=50000, E=800000, dims 64/128/2.
#define MAXN 50176                     // 392 * 128, padded
#define MAXE 800000

// -------- device scratch (no allocations allowed) --------
__device__ __half g_xwh[MAXN * 128];   // conv GEMM output (fp16) - gathered by agg
__device__ __half g_H[MAXN * 384];     // concat hidden (fp16)
__device__ __half g_x16[MAXN * 64];    // x in fp16
__device__ float  g_out2[MAXN * 2];    // fused MLP partial sums
__device__ __half g_W1h[128 * 64],  g_W1l[128 * 64];    // [out][in] fp16 hi/lo
__device__ __half g_W2h[128 * 128], g_W2l[128 * 128];
__device__ __half g_W3h[128 * 128], g_W3l[128 * 128];
__device__ __half g_L1h[384 * 384], g_L1l[384 * 384];   // lW1 already [out][in]
__device__ int   g_deg[MAXN];
__device__ float g_dinv[MAXN];
__device__ int   g_rp[MAXN + 1];
__device__ int   g_cur[MAXN];
__device__ int   g_col[MAXE];
__device__ float g_wf[MAXE];           // dinv[src]*dinv[dst] per CSR slot
__device__ int   g_bsums[64];

// ======================= helpers =======================

__device__ __forceinline__ uint32_t s2u(const void* p) {
    uint32_t a;
    asm("{ .reg .u64 t; cvta.to.shared.u64 t, %1; cvt.u32.u64 %0, t; }" : "=r"(a) : "l"(p));
    return a;
}

__device__ __forceinline__ void cpa16(uint32_t sdst, const void* gsrc) {
    asm volatile("cp.async.cg.shared.global [%0], [%1], 16;" :: "r"(sdst), "l"(gsrc) : "memory");
}
__device__ __forceinline__ void cpa_commit() {
    asm volatile("cp.async.commit_group;" ::: "memory");
}
template <int N>
__device__ __forceinline__ void cpa_wait() {
    asm volatile("cp.async.wait_group %0;" :: "n"(N) : "memory");
}

__device__ __forceinline__ void ldsm4(uint32_t& r0, uint32_t& r1, uint32_t& r2, uint32_t& r3,
                                      uint32_t addr) {
    asm volatile("ldmatrix.sync.aligned.m8n8.x4.shared.b16 {%0,%1,%2,%3}, [%4];"
                 : "=r"(r0), "=r"(r1), "=r"(r2), "=r"(r3) : "r"(addr));
}

__device__ __forceinline__ void mma_h(float* c, uint32_t a0, uint32_t a1, uint32_t a2,
                                      uint32_t a3, uint32_t b0, uint32_t b1) {
    asm volatile(
        "mma.sync.aligned.m16n8k16.row.col.f32.f16.f16.f32 "
        "{%0,%1,%2,%3}, {%4,%5,%6,%7}, {%8,%9}, {%0,%1,%2,%3};"
        : "+f"(c[0]), "+f"(c[1]), "+f"(c[2]), "+f"(c[3])
        : "r"(a0), "r"(a1), "r"(a2), "r"(a3), "r"(b0), "r"(b1));
}

__device__ __forceinline__ void wsplit(float x, __half& h, __half& l) {
    h = __float2half_rn(x);
    l = __float2half_rn(x - __half2float(h));
}

// ======================= graph preprocessing =======================

__global__ void k_zero(int n) {
    int i = blockIdx.x * blockDim.x + threadIdx.x;
    if (i < n) g_deg[i] = 0;
}
__global__ void k_deg(const int* __restrict__ dst, int e) {
    int i = blockIdx.x * blockDim.x + threadIdx.x;
    if (i < e) atomicAdd(&g_deg[dst[i]], 1);
}
__global__ void k_scan1(int n) {
    __shared__ int sh[1024];
    int i = blockIdx.x * 1024 + threadIdx.x;
    int v = (i < n) ? g_deg[i] : 0;
    if (i < n) g_dinv[i] = rsqrtf((float)(v + 1));   // fused dinv
    sh[threadIdx.x] = v;
    __syncthreads();
    for (int o = 1; o < 1024; o <<= 1) {
        int t = (threadIdx.x >= o) ? sh[threadIdx.x - o] : 0;
        __syncthreads();
        sh[threadIdx.x] += t;
        __syncthreads();
    }
    int incl = sh[threadIdx.x];
    if (i < n) g_rp[i] = incl - v;
    if (threadIdx.x == 1023) g_bsums[blockIdx.x] = incl;
}
// scan3 with scan2 folded in: every block redundantly exclusive-scans bsums.
__global__ void k_scan3(int n, int e, int nb) {
    __shared__ int sh[64];
    if (threadIdx.x < 64) sh[threadIdx.x] = (threadIdx.x < nb) ? g_bsums[threadIdx.x] : 0;
    __syncthreads();
    if (threadIdx.x == 0) {
        int run = 0;
        for (int b = 0; b < 64; ++b) { int t = sh[b]; sh[b] = run; run += t; }
    }
    __syncthreads();
    int i = blockIdx.x * 1024 + threadIdx.x;
    if (i < n) {
        int v = g_rp[i] + sh[blockIdx.x];
        g_rp[i] = v;
        g_cur[i] = v;
    }
    if (i == 0) g_rp[n] = e;
}
__global__ void k_fill(const int* __restrict__ src, const int* __restrict__ dst, int e) {
    int i = blockIdx.x * blockDim.x + threadIdx.x;
    if (i < e) {
        int s = src[i], d = dst[i];
        int p = atomicAdd(&g_cur[d], 1);
        g_col[p] = s;
        g_wf[p] = g_dinv[s] * g_dinv[d];
    }
}

// ======================= pre-conversion =======================

__global__ void k_cvt_x(const float* __restrict__ x, int n) {
    int i = blockIdx.x * blockDim.x + threadIdx.x;     // float4 groups: MAXN*16
    if (i >= MAXN * 16) return;
    int row = i >> 4;
    int c4 = (i & 15) << 2;
    float4 v = make_float4(0.f, 0.f, 0.f, 0.f);
    if (row < n) v = *(const float4*)(x + (size_t)row * 64 + c4);
    size_t o = (size_t)row * 64 + c4;
    *(__half2*)(g_x16 + o)     = __floats2half2_rn(v.x, v.y);
    *(__half2*)(g_x16 + o + 2) = __floats2half2_rn(v.z, v.w);
    if ((i & 15) == 0) {                // one thread per row zeroes g_out2
        g_out2[2 * row] = 0.f;
        g_out2[2 * row + 1] = 0.f;
    }
}

__global__ void k_cvt_w(const float* __restrict__ W1, const float* __restrict__ W2,
                        const float* __restrict__ W3, const float* __restrict__ L1) {
    int i = blockIdx.x * blockDim.x + threadIdx.x;
    if (i < 8192) {                      // W1: [64][128] -> [128][64]
        int o = i / 64, k = i % 64;
        wsplit(W1[(size_t)k * 128 + o], g_W1h[i], g_W1l[i]);
    } else if (i < 24576) {              // W2: [128][128] -> T
        int j = i - 8192;
        int o = j / 128, k = j % 128;
        wsplit(W2[(size_t)k * 128 + o], g_W2h[j], g_W2l[j]);
    } else if (i < 40960) {              // W3
        int j = i - 24576;
        int o = j / 128, k = j % 128;
        wsplit(W3[(size_t)k * 128 + o], g_W3h[j], g_W3l[j]);
    } else if (i < 188416) {             // lW1 straight copy-split
        int j = i - 40960;
        wsplit(L1[j], g_L1h[j], g_L1l[j]);
    }
}

// ======= fp16 GEMM: A single plane, B hi/lo (2-term), 3-stage pipeline ======
// BM=128, BN=128 (R12 proven config).
// EPI==0: fp16 store. EPI==2: fused MLP tail -> g_out2.

#define PITCH 80
#define PLANE (128 * PITCH)            // 10240
#define STG (3 * PLANE)                // 30720
#define SM_TOTAL (3 * STG)             // 92160

template <int EPI>
__global__ __launch_bounds__(256, 2)
void mm3(const __half* __restrict__ A, int lda,
         const __half* __restrict__ Bh, const __half* __restrict__ Bl, int ldb,
         __half* __restrict__ C, int ldc, const float* __restrict__ bias,
         const float* __restrict__ w2, int K)
{
    extern __shared__ char smem[];
    uint32_t sb = s2u(smem);
    int tid = threadIdx.x;
    int lane = tid & 31;
    int wid = tid >> 5;
    int warp_m = wid & 3;
    int warp_n = wid >> 2;

    int bm = blockIdx.x * 128;
    int bn = blockIdx.y * 128;

    float acc[2][8][4];
#pragma unroll
    for (int a = 0; a < 2; ++a)
#pragma unroll
        for (int b = 0; b < 8; ++b)
#pragma unroll
            for (int c = 0; c < 4; ++c) acc[a][b][c] = 0.f;

    int a_r = (lane & 7) + ((lane & 8) ? 8 : 0);
    int a_c8 = (lane & 16) ? 8 : 0;
    int b_r = (lane & 7) + ((lane & 16) ? 8 : 0);
    int b_c8 = (lane & 8) ? 8 : 0;

    int nch = K >> 5;      // 32-wide K chunks

    auto issue = [&](int ch) {
        int k0 = ch << 5;
        uint32_t base = sb + (ch % 3) * STG;
#pragma unroll
        for (int t = tid; t < 512; t += 256) {
            int row = t >> 2;
            int c = (t & 3) << 4;                  // 0,16,32,48 bytes
            uint32_t d = base + row * PITCH + c;
            cpa16(d,             (const char*)(A  + (size_t)(bm + row) * lda + k0) + c);
            cpa16(d + PLANE,     (const char*)(Bh + (size_t)(bn + row) * ldb + k0) + c);
            cpa16(d + 2 * PLANE, (const char*)(Bl + (size_t)(bn + row) * ldb + k0) + c);
        }
        cpa_commit();
    };

    issue(0);
    if (nch > 1) issue(1);
    for (int ch = 0; ch < nch; ++ch) {
        if (ch + 2 < nch) {
            issue(ch + 2);
            cpa_wait<2>();
        } else if (ch + 1 < nch) {
            cpa_wait<1>();
        } else {
            cpa_wait<0>();
        }
        __syncthreads();

        uint32_t pA  = sb + (ch % 3) * STG;
        uint32_t pBH = pA + PLANE;
        uint32_t pBL = pA + 2 * PLANE;

#pragma unroll
        for (int k16 = 0; k16 < 2; ++k16) {
            int kb = k16 * 16;
            uint32_t ah[2][4];
#pragma unroll
            for (int mt = 0; mt < 2; ++mt) {
                int rr = warp_m * 32 + mt * 16 + a_r;
                uint32_t off = (uint32_t)(rr * PITCH + (kb + a_c8) * 2);
                ldsm4(ah[mt][0], ah[mt][1], ah[mt][2], ah[mt][3], pA + off);
            }
#pragma unroll
            for (int half = 0; half < 2; ++half) {
                uint32_t bh[4][2], bl[4][2];
#pragma unroll
                for (int pair = 0; pair < 2; ++pair) {
                    int nn = warp_n * 64 + half * 32 + pair * 16 + b_r;
                    uint32_t off = (uint32_t)(nn * PITCH + (kb + b_c8) * 2);
                    ldsm4(bh[pair * 2][0], bh[pair * 2][1],
                          bh[pair * 2 + 1][0], bh[pair * 2 + 1][1], pBH + off);
                    ldsm4(bl[pair * 2][0], bl[pair * 2][1],
                          bl[pair * 2 + 1][0], bl[pair * 2 + 1][1], pBL + off);
                }
#pragma unroll
                for (int mt = 0; mt < 2; ++mt) {
#pragma unroll
                    for (int nt = 0; nt < 4; ++nt) {
                        float* c = acc[mt][half * 4 + nt];
                        mma_h(c, ah[mt][0], ah[mt][1], ah[mt][2], ah[mt][3],
                              bh[nt][0], bh[nt][1]);
                        mma_h(c, ah[mt][0], ah[mt][1], ah[mt][2], ah[mt][3],
                              bl[nt][0], bl[nt][1]);
                    }
                }
            }
        }
        __syncthreads();
    }

    int gid = lane >> 2;
    int tig = lane & 3;

    if (EPI == 2) {
        float p[2][2][2] = {};                      // [mt][row half][out]
#pragma unroll
        for (int g = 0; g < 8; ++g) {
            int col = bn + warp_n * 64 + g * 8 + tig * 2;
            float bb0 = __ldg(bias + col), bb1 = __ldg(bias + col + 1);
            float w00 = __ldg(w2 + col),       w01 = __ldg(w2 + col + 1);
            float w10 = __ldg(w2 + 384 + col), w11 = __ldg(w2 + 385 + col);
#pragma unroll
            for (int mt = 0; mt < 2; ++mt) {
                float* c = acc[mt][g];
                float v0 = fmaxf(c[0] + bb0, 0.f);
                float v1 = fmaxf(c[1] + bb1, 0.f);
                float v2 = fmaxf(c[2] + bb0, 0.f);
                float v3 = fmaxf(c[3] + bb1, 0.f);
                p[mt][0][0] += v0 * w00 + v1 * w01;
                p[mt][0][1] += v0 * w10 + v1 * w11;
                p[mt][1][0] += v2 * w00 + v3 * w01;
                p[mt][1][1] += v2 * w10 + v3 * w11;
            }
        }
#pragma unroll
        for (int mt = 0; mt < 2; ++mt)
#pragma unroll
            for (int r = 0; r < 2; ++r)
#pragma unroll
                for (int o = 0; o < 2; ++o) {
                    float v = p[mt][r][o];
                    v += __shfl_xor_sync(0xFFFFFFFFu, v, 1);
                    v += __shfl_xor_sync(0xFFFFFFFFu, v, 2);
                    p[mt][r][o] = v;
                }
        if (tig == 0) {
#pragma unroll
            for (int mt = 0; mt < 2; ++mt) {
                int row0 = bm + warp_m * 32 + mt * 16 + gid;
                atomicAdd(&g_out2[2 * row0 + 0], p[mt][0][0]);
                atomicAdd(&g_out2[2 * row0 + 1], p[mt][0][1]);
                atomicAdd(&g_out2[2 * (row0 + 8) + 0], p[mt][1][0]);
                atomicAdd(&g_out2[2 * (row0 + 8) + 1], p[mt][1][1]);
            }
        }
        return;
    }

#pragma unroll
    for (int mt = 0; mt < 2; ++mt) {
        int row0 = bm + warp_m * 32 + mt * 16 + gid;
#pragma unroll
        for (int g = 0; g < 8; ++g) {
            int col = bn + warp_n * 64 + g * 8 + tig * 2;
            float* c = acc[mt][g];
            *(__half2*)(C + (size_t)row0 * ldc + col)       = __floats2half2_rn(c[0], c[1]);
            *(__half2*)(C + (size_t)(row0 + 8) * ldc + col) = __floats2half2_rn(c[2], c[3]);
        }
    }
}

// ======================= edge aggregation (fp16 gather -> fp16 H) ===========

__global__ void k_agg(const float* __restrict__ bias, int off, int n)
{
    int warp = (blockIdx.x * blockDim.x + threadIdx.x) >> 5;
    int lane = threadIdx.x & 31;
    if (warp >= n) return;
    const uint2* xw2 = (const uint2*)g_xwh;     // 32 uint2 per row

    float di = g_dinv[warp];
    float w0 = di * di;
    uint2 ra = xw2[(size_t)warp * 32 + lane];
    float2 a0 = __half22float2(*(__half2*)&ra.x);
    float2 a1 = __half22float2(*(__half2*)&ra.y);
    float s0f = w0 * a0.x, s1f = w0 * a0.y, s2f = w0 * a1.x, s3f = w0 * a1.y;

    int s0 = g_rp[warp], s1 = g_rp[warp + 1];
    int j = s0;
    for (; j + 3 < s1; j += 4) {
        int i0 = g_col[j], i1 = g_col[j + 1], i2 = g_col[j + 2], i3 = g_col[j + 3];
        float u0 = g_wf[j], u1 = g_wf[j + 1], u2 = g_wf[j + 2], u3 = g_wf[j + 3];
        uint2 r0 = xw2[(size_t)i0 * 32 + lane];
        uint2 r1 = xw2[(size_t)i1 * 32 + lane];
        uint2 r2 = xw2[(size_t)i2 * 32 + lane];
        uint2 r3 = xw2[(size_t)i3 * 32 + lane];
        float2 p;
        p = __half22float2(*(__half2*)&r0.x); s0f += u0 * p.x; s1f += u0 * p.y;
        p = __half22float2(*(__half2*)&r0.y); s2f += u0 * p.x; s3f += u0 * p.y;
        p = __half22float2(*(__half2*)&r1.x); s0f += u1 * p.x; s1f += u1 * p.y;
        p = __half22float2(*(__half2*)&r1.y); s2f += u1 * p.x; s3f += u1 * p.y;
        p = __half22float2(*(__half2*)&r2.x); s0f += u2 * p.x; s1f += u2 * p.y;
        p = __half22float2(*(__half2*)&r2.y); s2f += u2 * p.x; s3f += u2 * p.y;
        p = __half22float2(*(__half2*)&r3.x); s0f += u3 * p.x; s1f += u3 * p.y;
        p = __half22float2(*(__half2*)&r3.y); s2f += u3 * p.x; s3f += u3 * p.y;
    }
    for (; j < s1; ++j) {
        int s = g_col[j];
        float w = g_wf[j];
        uint2 r = xw2[(size_t)s * 32 + lane];
        float2 p;
        p = __half22float2(*(__half2*)&r.x); s0f += w * p.x; s1f += w * p.y;
        p = __half22float2(*(__half2*)&r.y); s2f += w * p.x; s3f += w * p.y;
    }
    const float4 b4 = ((const float4*)bias)[lane];
    s0f += b4.x; s1f += b4.y; s2f += b4.z; s3f += b4.w;

    size_t o = (size_t)warp * 384 + off + lane * 4;
    *(__half2*)(g_H + o)     = __floats2half2_rn(s0f, s1f);
    *(__half2*)(g_H + o + 2) = __floats2half2_rn(s2f, s3f);
}

// ======================= final: bias + softmax from fused partials ==========

__global__ void k_final2(const float* __restrict__ lb2, float* __restrict__ out, int n)
{
    int i = blockIdx.x * blockDim.x + threadIdx.x;
    if (i >= n) return;
    float a0 = g_out2[2 * i] + lb2[0];
    float a1 = g_out2[2 * i + 1] + lb2[1];
    out[2 * i] = a0;
    out[2 * i + 1] = a1;
    float m = fmaxf(a0, a1);
    float e0 = expf(a0 - m), e1 = expf(a1 - m);
    float inv = 1.f / (e0 + e1);
    out[(size_t)2 * n + 2 * i] = e0 * inv;
    out[(size_t)2 * n + 2 * i + 1] = e1 * inv;
}

// ======================= launch =======================

extern "C" void kernel_launch(void* const* d_in, const int* in_sizes, int n_in,
                              void* d_out, int out_size)
{
    const float* x   = (const float*)d_in[0];
    const int*   ei  = (const int*)  d_in[1];
    const float* W1  = (const float*)d_in[2];
    const float* b1  = (const float*)d_in[3];
    const float* W2  = (const float*)d_in[4];
    const float* b2  = (const float*)d_in[5];
    const float* W3  = (const float*)d_in[6];
    const float* b3  = (const float*)d_in[7];
    const float* lW1 = (const float*)d_in[8];
    const float* lb1 = (const float*)d_in[9];
    const float* lW2 = (const float*)d_in[10];
    const float* lb2 = (const float*)d_in[11];
    float* out = (float*)d_out;

    int n = in_sizes[0] / 64;   // 50000
    int e = in_sizes[1] / 2;    // 800000
    const int* src = ei;
    const int* dst = ei + e;

    void *p_xwh, *p_H, *p_x16;
    void *p_W1h, *p_W1l, *p_W2h, *p_W2l, *p_W3h, *p_W3l, *p_L1h, *p_L1l;
    cudaGetSymbolAddress(&p_xwh, g_xwh);
    cudaGetSymbolAddress(&p_H,   g_H);
    cudaGetSymbolAddress(&p_x16, g_x16);
    cudaGetSymbolAddress(&p_W1h, g_W1h); cudaGetSymbolAddress(&p_W1l, g_W1l);
    cudaGetSymbolAddress(&p_W2h, g_W2h); cudaGetSymbolAddress(&p_W2l, g_W2l);
    cudaGetSymbolAddress(&p_W3h, g_W3h); cudaGetSymbolAddress(&p_W3l, g_W3l);
    cudaGetSymbolAddress(&p_L1h, g_L1h); cudaGetSymbolAddress(&p_L1l, g_L1l);
    __half* H   = (__half*)p_H;
    __half* xwh = (__half*)p_xwh;

    cudaFuncSetAttribute(mm3<0>, cudaFuncAttributeMaxDynamicSharedMemorySize, SM_TOTAL);
    cudaFuncSetAttribute(mm3<2>, cudaFuncAttributeMaxDynamicSharedMemorySize, SM_TOTAL);

    // one-time side stream + fork/join events (host resources, not device mem)
    static cudaStream_t s2 = nullptr;
    static cudaEvent_t evFork = nullptr, evJoin = nullptr;
    if (!s2) {
        cudaStreamCreateWithFlags(&s2, cudaStreamNonBlocking);
        cudaEventCreateWithFlags(&evFork, cudaEventDisableTiming);
        cudaEventCreateWithFlags(&evJoin, cudaEventDisableTiming);
    }

    int nb = (n + 1023) / 1024;
    int gm = MAXN / 128;               // 392
    int aggBlocks = (n + 7) / 8;

    // ---- fork: CSR branch on s2, convert+conv1 on main ----
    cudaEventRecord(evFork, 0);
    cudaStreamWaitEvent(s2, evFork, 0);

    k_zero<<<(n + 255) / 256, 256, 0, s2>>>(n);
    k_deg<<<(e + 255) / 256, 256, 0, s2>>>(dst, e);

    k_cvt_x<<<(MAXN * 16 + 255) / 256, 256>>>(x, n);
    k_cvt_w<<<(188416 + 255) / 256, 256>>>(W1, W2, W3, lW1);

    k_scan1<<<nb, 1024, 0, s2>>>(n);
    k_scan3<<<nb, 1024, 0, s2>>>(n, e, nb);
    k_fill<<<(e + 255) / 256, 256, 0, s2>>>(src, dst, e);
    cudaEventRecord(evJoin, s2);

    // conv1
    mm3<0><<<dim3(gm, 1), 256, SM_TOTAL>>>((__half*)p_x16, 64,
                                           (__half*)p_W1h, (__half*)p_W1l, 64,
                                           xwh, 128, nullptr, nullptr, 64);

    cudaStreamWaitEvent(0, evJoin, 0);

    // conv1 aggregation
    k_agg<<<aggBlocks, 256>>>(b1, 0, n);
    // conv2
    mm3<0><<<dim3(gm, 1), 256, SM_TOTAL>>>(H, 384,
                                           (__half*)p_W2h, (__half*)p_W2l, 128,
                                           xwh, 128, nullptr, nullptr, 128);
    k_agg<<<aggBlocks, 256>>>(b2, 128, n);
    // conv3
    mm3<0><<<dim3(gm, 1), 256, SM_TOTAL>>>(H + 128, 384,
                                           (__half*)p_W3h, (__half*)p_W3l, 128,
                                           xwh, 128, nullptr, nullptr, 128);
    k_agg<<<aggBlocks, 256>>>(b3, 256, n);

    // MLP fused: partial relu(H@lW1^T+lb1) @ lW2^T accumulated into g_out2
    mm3<2><<<dim3(gm, 3), 256, SM_TOTAL>>>(H, 384,
                                           (__half*)p_L1h, (__half*)p_L1l, 384,
                                           nullptr, 0, lb1, lW2, 384);

    // bias + softmax
    k_final2<<<(n + 255) / 256, 256>>>(lb2, out, n);
}

// round 17
// speedup vs baseline: 1.7590x; 1.4967x over previous
#include <cuda_runtime.h>
#include <cuda_bf16.h>
#include <cuda_fp16.h>
#include <cstdint>

// Problem constants: N=50000, E=800000, dims 64/128/2.
#define MAXN 50176                     // 392 * 128, padded
#define MAXE 800000

// -------- device scratch (no allocations allowed) --------
__device__ __half g_xwh[MAXN * 128];   // conv GEMM output (fp16) - gathered by agg
__device__ __half g_H[MAXN * 384];     // concat hidden (fp16)
__device__ __half g_x16[MAXN * 64];    // x in fp16
__device__ float  g_out2[MAXN * 2];    // fused MLP partial sums
__device__ __half g_W1h[128 * 64],  g_W1l[128 * 64];    // [out][in] fp16 hi/lo
__device__ __half g_W2h[128 * 128], g_W2l[128 * 128];
__device__ __half g_W3h[128 * 128], g_W3l[128 * 128];
__device__ __half g_L1h[384 * 384], g_L1l[384 * 384];   // lW1 already [out][in]
__device__ int   g_deg[MAXN];
__device__ float g_dinv[MAXN];
__device__ int   g_rp[MAXN + 1];
__device__ int   g_cur[MAXN];
__device__ int   g_col[MAXE];
__device__ float g_wf[MAXE];           // dinv[src]*dinv[dst] per CSR slot
__device__ int   g_bsums[64];

// ======================= helpers =======================

__device__ __forceinline__ uint32_t s2u(const void* p) {
    uint32_t a;
    asm("{ .reg .u64 t; cvta.to.shared.u64 t, %1; cvt.u32.u64 %0, t; }" : "=r"(a) : "l"(p));
    return a;
}

__device__ __forceinline__ void cpa16(uint32_t sdst, const void* gsrc) {
    asm volatile("cp.async.cg.shared.global [%0], [%1], 16;" :: "r"(sdst), "l"(gsrc) : "memory");
}
__device__ __forceinline__ void cpa_commit() {
    asm volatile("cp.async.commit_group;" ::: "memory");
}
template <int N>
__device__ __forceinline__ void cpa_wait() {
    asm volatile("cp.async.wait_group %0;" :: "n"(N) : "memory");
}

__device__ __forceinline__ void ldsm4(uint32_t& r0, uint32_t& r1, uint32_t& r2, uint32_t& r3,
                                      uint32_t addr) {
    asm volatile("ldmatrix.sync.aligned.m8n8.x4.shared.b16 {%0,%1,%2,%3}, [%4];"
                 : "=r"(r0), "=r"(r1), "=r"(r2), "=r"(r3) : "r"(addr));
}

__device__ __forceinline__ void mma_h(float* c, uint32_t a0, uint32_t a1, uint32_t a2,
                                      uint32_t a3, uint32_t b0, uint32_t b1) {
    asm volatile(
        "mma.sync.aligned.m16n8k16.row.col.f32.f16.f16.f32 "
        "{%0,%1,%2,%3}, {%4,%5,%6,%7}, {%8,%9}, {%0,%1,%2,%3};"
        : "+f"(c[0]), "+f"(c[1]), "+f"(c[2]), "+f"(c[3])
        : "r"(a0), "r"(a1), "r"(a2), "r"(a3), "r"(b0), "r"(b1));
}

__device__ __forceinline__ void wsplit(float x, __half& h, __half& l) {
    h = __float2half_rn(x);
    l = __float2half_rn(x - __half2float(h));
}

// ======================= graph preprocessing =======================

__global__ void k_zero(int n) {
    int i = blockIdx.x * blockDim.x + threadIdx.x;
    if (i < MAXN) {
        if (i < n) g_deg[i] = 0;
        g_out2[2 * i] = 0.f;
        g_out2[2 * i + 1] = 0.f;
    }
}
__global__ void k_deg(const int* __restrict__ dst, int e) {
    int i = blockIdx.x * blockDim.x + threadIdx.x;
    if (i < e) atomicAdd(&g_deg[dst[i]], 1);
}
__global__ void k_scan1(int n) {
    __shared__ int sh[1024];
    int i = blockIdx.x * 1024 + threadIdx.x;
    int v = (i < n) ? g_deg[i] : 0;
    if (i < n) g_dinv[i] = rsqrtf((float)(v + 1));   // fused dinv
    sh[threadIdx.x] = v;
    __syncthreads();
    for (int o = 1; o < 1024; o <<= 1) {
        int t = (threadIdx.x >= o) ? sh[threadIdx.x - o] : 0;
        __syncthreads();
        sh[threadIdx.x] += t;
        __syncthreads();
    }
    int incl = sh[threadIdx.x];
    if (i < n) g_rp[i] = incl - v;
    if (threadIdx.x == 1023) g_bsums[blockIdx.x] = incl;
}
__global__ void k_scan2(int nb) {
    __shared__ int sh[64];
    int v = (threadIdx.x < nb) ? g_bsums[threadIdx.x] : 0;
    sh[threadIdx.x] = v;
    __syncthreads();
    for (int o = 1; o < 64; o <<= 1) {
        int t = (threadIdx.x >= o) ? sh[threadIdx.x - o] : 0;
        __syncthreads();
        sh[threadIdx.x] += t;
        __syncthreads();
    }
    if (threadIdx.x < nb) g_bsums[threadIdx.x] = sh[threadIdx.x] - v;
}
__global__ void k_scan3(int n, int e) {
    int i = blockIdx.x * 1024 + threadIdx.x;
    if (i < n) {
        int v = g_rp[i] + g_bsums[blockIdx.x];
        g_rp[i] = v;
        g_cur[i] = v;
    }
    if (i == 0) g_rp[n] = e;
}
__global__ void k_fill(const int* __restrict__ src, const int* __restrict__ dst, int e) {
    int i = blockIdx.x * blockDim.x + threadIdx.x;
    if (i < e) {
        int s = src[i], d = dst[i];
        int p = atomicAdd(&g_cur[d], 1);
        g_col[p] = s;
        g_wf[p] = g_dinv[s] * g_dinv[d];
    }
}

// ======================= pre-conversion =======================

__global__ void k_cvt_x(const float* __restrict__ x, int n) {
    int i = blockIdx.x * blockDim.x + threadIdx.x;     // float4 groups: MAXN*16
    if (i >= MAXN * 16) return;
    int row = i >> 4;
    int c4 = (i & 15) << 2;
    float4 v = make_float4(0.f, 0.f, 0.f, 0.f);
    if (row < n) v = *(const float4*)(x + (size_t)row * 64 + c4);
    size_t o = (size_t)row * 64 + c4;
    *(__half2*)(g_x16 + o)     = __floats2half2_rn(v.x, v.y);
    *(__half2*)(g_x16 + o + 2) = __floats2half2_rn(v.z, v.w);
}

__global__ void k_cvt_w(const float* __restrict__ W1, const float* __restrict__ W2,
                        const float* __restrict__ W3, const float* __restrict__ L1) {
    int i = blockIdx.x * blockDim.x + threadIdx.x;
    if (i < 8192) {                      // W1: [64][128] -> [128][64]
        int o = i / 64, k = i % 64;
        wsplit(W1[(size_t)k * 128 + o], g_W1h[i], g_W1l[i]);
    } else if (i < 24576) {              // W2: [128][128] -> T
        int j = i - 8192;
        int o = j / 128, k = j % 128;
        wsplit(W2[(size_t)k * 128 + o], g_W2h[j], g_W2l[j]);
    } else if (i < 40960) {              // W3
        int j = i - 24576;
        int o = j / 128, k = j % 128;
        wsplit(W3[(size_t)k * 128 + o], g_W3h[j], g_W3l[j]);
    } else if (i < 188416) {             // lW1 straight copy-split
        int j = i - 40960;
        wsplit(L1[j], g_L1h[j], g_L1l[j]);
    }
}

// ======= fp16 GEMM: A single plane, B hi/lo (2-term), 3-stage pipeline ======
// EPI==0: plain store (HALFOUT selects fp16/fp32 C).
// EPI==2: fused MLP tail — relu(v+lb1) dotted with lW2 rows, atomicAdd to g_out2.

#define PITCH 80
#define PLANE (128 * PITCH)            // 10240
#define STG (3 * PLANE)                // 30720
#define SM_TOTAL (3 * STG)             // 92160

template <int EPI, int HALFOUT>
__global__ __launch_bounds__(256, 2)
void mm3(const __half* __restrict__ A, int lda,
         const __half* __restrict__ Bh, const __half* __restrict__ Bl, int ldb,
         void* __restrict__ Cv, int ldc, const float* __restrict__ bias,
         const float* __restrict__ w2, int K)
{
    extern __shared__ char smem[];
    uint32_t sb = s2u(smem);
    int tid = threadIdx.x;
    int lane = tid & 31;
    int wid = tid >> 5;
    int warp_m = wid & 3;
    int warp_n = wid >> 2;

    int bm = blockIdx.x * 128;
    int bn = blockIdx.y * 128;

    float acc[2][8][4];
#pragma unroll
    for (int a = 0; a < 2; ++a)
#pragma unroll
        for (int b = 0; b < 8; ++b)
#pragma unroll
            for (int c = 0; c < 4; ++c) acc[a][b][c] = 0.f;

    int a_r = (lane & 7) + ((lane & 8) ? 8 : 0);
    int a_c8 = (lane & 16) ? 8 : 0;
    int b_r = (lane & 7) + ((lane & 16) ? 8 : 0);
    int b_c8 = (lane & 8) ? 8 : 0;

    int nch = K >> 5;      // 32-wide K chunks

    auto issue = [&](int ch) {
        int k0 = ch << 5;
        uint32_t base = sb + (ch % 3) * STG;
#pragma unroll
        for (int t = tid; t < 512; t += 256) {
            int row = t >> 2;
            int c = (t & 3) << 4;                  // 0,16,32,48 bytes
            uint32_t d = base + row * PITCH + c;
            cpa16(d,             (const char*)(A  + (size_t)(bm + row) * lda + k0) + c);
            cpa16(d + PLANE,     (const char*)(Bh + (size_t)(bn + row) * ldb + k0) + c);
            cpa16(d + 2 * PLANE, (const char*)(Bl + (size_t)(bn + row) * ldb + k0) + c);
        }
        cpa_commit();
    };

    issue(0);
    if (nch > 1) issue(1);
    for (int ch = 0; ch < nch; ++ch) {
        if (ch + 2 < nch) {
            issue(ch + 2);
            cpa_wait<2>();
        } else if (ch + 1 < nch) {
            cpa_wait<1>();
        } else {
            cpa_wait<0>();
        }
        __syncthreads();

        uint32_t pA  = sb + (ch % 3) * STG;
        uint32_t pBH = pA + PLANE;
        uint32_t pBL = pA + 2 * PLANE;

#pragma unroll
        for (int k16 = 0; k16 < 2; ++k16) {
            int kb = k16 * 16;
            uint32_t ah[2][4];
#pragma unroll
            for (int mt = 0; mt < 2; ++mt) {
                int rr = warp_m * 32 + mt * 16 + a_r;
                uint32_t off = (uint32_t)(rr * PITCH + (kb + a_c8) * 2);
                ldsm4(ah[mt][0], ah[mt][1], ah[mt][2], ah[mt][3], pA + off);
            }
#pragma unroll
            for (int half = 0; half < 2; ++half) {
                uint32_t bh[4][2], bl[4][2];
#pragma unroll
                for (int pair = 0; pair < 2; ++pair) {
                    int nn = warp_n * 64 + half * 32 + pair * 16 + b_r;
                    uint32_t off = (uint32_t)(nn * PITCH + (kb + b_c8) * 2);
                    ldsm4(bh[pair * 2][0], bh[pair * 2][1],
                          bh[pair * 2 + 1][0], bh[pair * 2 + 1][1], pBH + off);
                    ldsm4(bl[pair * 2][0], bl[pair * 2][1],
                          bl[pair * 2 + 1][0], bl[pair * 2 + 1][1], pBL + off);
                }
#pragma unroll
                for (int mt = 0; mt < 2; ++mt) {
#pragma unroll
                    for (int nt = 0; nt < 4; ++nt) {
                        float* c = acc[mt][half * 4 + nt];
                        mma_h(c, ah[mt][0], ah[mt][1], ah[mt][2], ah[mt][3],
                              bh[nt][0], bh[nt][1]);
                        mma_h(c, ah[mt][0], ah[mt][1], ah[mt][2], ah[mt][3],
                              bl[nt][0], bl[nt][1]);
                    }
                }
            }
        }
        __syncthreads();
    }

    int gid = lane >> 2;
    int tig = lane & 3;

    if (EPI == 2) {
        float p[2][2][2] = {};                      // [mt][row half][out]
#pragma unroll
        for (int g = 0; g < 8; ++g) {
            int col = bn + warp_n * 64 + g * 8 + tig * 2;
            float bb0 = __ldg(bias + col), bb1 = __ldg(bias + col + 1);
            float w00 = __ldg(w2 + col),       w01 = __ldg(w2 + col + 1);
            float w10 = __ldg(w2 + 384 + col), w11 = __ldg(w2 + 385 + col);
#pragma unroll
            for (int mt = 0; mt < 2; ++mt) {
                float* c = acc[mt][g];
                float v0 = fmaxf(c[0] + bb0, 0.f);
                float v1 = fmaxf(c[1] + bb1, 0.f);
                float v2 = fmaxf(c[2] + bb0, 0.f);
                float v3 = fmaxf(c[3] + bb1, 0.f);
                p[mt][0][0] += v0 * w00 + v1 * w01;
                p[mt][0][1] += v0 * w10 + v1 * w11;
                p[mt][1][0] += v2 * w00 + v3 * w01;
                p[mt][1][1] += v2 * w10 + v3 * w11;
            }
        }
#pragma unroll
        for (int mt = 0; mt < 2; ++mt)
#pragma unroll
            for (int r = 0; r < 2; ++r)
#pragma unroll
                for (int o = 0; o < 2; ++o) {
                    float v = p[mt][r][o];
                    v += __shfl_xor_sync(0xFFFFFFFFu, v, 1);
                    v += __shfl_xor_sync(0xFFFFFFFFu, v, 2);
                    p[mt][r][o] = v;
                }
        if (tig == 0) {
#pragma unroll
            for (int mt = 0; mt < 2; ++mt) {
                int row0 = bm + warp_m * 32 + mt * 16 + gid;
                atomicAdd(&g_out2[2 * row0 + 0], p[mt][0][0]);
                atomicAdd(&g_out2[2 * row0 + 1], p[mt][0][1]);
                atomicAdd(&g_out2[2 * (row0 + 8) + 0], p[mt][1][0]);
                atomicAdd(&g_out2[2 * (row0 + 8) + 1], p[mt][1][1]);
            }
        }
        return;
    }

#pragma unroll
    for (int mt = 0; mt < 2; ++mt) {
        int row0 = bm + warp_m * 32 + mt * 16 + gid;
#pragma unroll
        for (int g = 0; g < 8; ++g) {
            int col = bn + warp_n * 64 + g * 8 + tig * 2;
            float* c = acc[mt][g];
            if (HALFOUT) {
                __half* C = (__half*)Cv;
                *(__half2*)(C + (size_t)row0 * ldc + col)       = __floats2half2_rn(c[0], c[1]);
                *(__half2*)(C + (size_t)(row0 + 8) * ldc + col) = __floats2half2_rn(c[2], c[3]);
            } else {
                float* C = (float*)Cv;
                *(float2*)(C + (size_t)row0 * ldc + col)       = make_float2(c[0], c[1]);
                *(float2*)(C + (size_t)(row0 + 8) * ldc + col) = make_float2(c[2], c[3]);
            }
        }
    }
}

// ======================= edge aggregation (fp16 gather -> fp16 H) ===========

__global__ void k_agg(const float* __restrict__ bias, int off, int n)
{
    int warp = (blockIdx.x * blockDim.x + threadIdx.x) >> 5;
    int lane = threadIdx.x & 31;
    if (warp >= n) return;
    const uint2* xw2 = (const uint2*)g_xwh;     // 32 uint2 per row

    float di = g_dinv[warp];
    float w0 = di * di;
    uint2 ra = xw2[(size_t)warp * 32 + lane];
    float2 a0 = __half22float2(*(__half2*)&ra.x);
    float2 a1 = __half22float2(*(__half2*)&ra.y);
    float s0f = w0 * a0.x, s1f = w0 * a0.y, s2f = w0 * a1.x, s3f = w0 * a1.y;

    int s0 = g_rp[warp], s1 = g_rp[warp + 1];
    int j = s0;
    for (; j + 3 < s1; j += 4) {
        int i0 = g_col[j], i1 = g_col[j + 1], i2 = g_col[j + 2], i3 = g_col[j + 3];
        float u0 = g_wf[j], u1 = g_wf[j + 1], u2 = g_wf[j + 2], u3 = g_wf[j + 3];
        uint2 r0 = xw2[(size_t)i0 * 32 + lane];
        uint2 r1 = xw2[(size_t)i1 * 32 + lane];
        uint2 r2 = xw2[(size_t)i2 * 32 + lane];
        uint2 r3 = xw2[(size_t)i3 * 32 + lane];
        float2 p;
        p = __half22float2(*(__half2*)&r0.x); s0f += u0 * p.x; s1f += u0 * p.y;
        p = __half22float2(*(__half2*)&r0.y); s2f += u0 * p.x; s3f += u0 * p.y;
        p = __half22float2(*(__half2*)&r1.x); s0f += u1 * p.x; s1f += u1 * p.y;
        p = __half22float2(*(__half2*)&r1.y); s2f += u1 * p.x; s3f += u1 * p.y;
        p = __half22float2(*(__half2*)&r2.x); s0f += u2 * p.x; s1f += u2 * p.y;
        p = __half22float2(*(__half2*)&r2.y); s2f += u2 * p.x; s3f += u2 * p.y;
        p = __half22float2(*(__half2*)&r3.x); s0f += u3 * p.x; s1f += u3 * p.y;
        p = __half22float2(*(__half2*)&r3.y); s2f += u3 * p.x; s3f += u3 * p.y;
    }
    for (; j < s1; ++j) {
        int s = g_col[j];
        float w = g_wf[j];
        uint2 r = xw2[(size_t)s * 32 + lane];
        float2 p;
        p = __half22float2(*(__half2*)&r.x); s0f += w * p.x; s1f += w * p.y;
        p = __half22float2(*(__half2*)&r.y); s2f += w * p.x; s3f += w * p.y;
    }
    const float4 b4 = ((const float4*)bias)[lane];
    s0f += b4.x; s1f += b4.y; s2f += b4.z; s3f += b4.w;

    size_t o = (size_t)warp * 384 + off + lane * 4;
    *(__half2*)(g_H + o)     = __floats2half2_rn(s0f, s1f);
    *(__half2*)(g_H + o + 2) = __floats2half2_rn(s2f, s3f);
}

// ======================= final: bias + softmax from fused partials ==========

__global__ void k_final2(const float* __restrict__ lb2, float* __restrict__ out, int n)
{
    int i = blockIdx.x * blockDim.x + threadIdx.x;
    if (i >= n) return;
    float a0 = g_out2[2 * i] + lb2[0];
    float a1 = g_out2[2 * i + 1] + lb2[1];
    out[2 * i] = a0;
    out[2 * i + 1] = a1;
    float m = fmaxf(a0, a1);
    float e0 = expf(a0 - m), e1 = expf(a1 - m);
    float inv = 1.f / (e0 + e1);
    out[(size_t)2 * n + 2 * i] = e0 * inv;
    out[(size_t)2 * n + 2 * i + 1] = e1 * inv;
}

// ======================= launch =======================

extern "C" void kernel_launch(void* const* d_in, const int* in_sizes, int n_in,
                              void* d_out, int out_size)
{
    const float* x   = (const float*)d_in[0];
    const int*   ei  = (const int*)  d_in[1];
    const float* W1  = (const float*)d_in[2];
    const float* b1  = (const float*)d_in[3];
    const float* W2  = (const float*)d_in[4];
    const float* b2  = (const float*)d_in[5];
    const float* W3  = (const float*)d_in[6];
    const float* b3  = (const float*)d_in[7];
    const float* lW1 = (const float*)d_in[8];
    const float* lb1 = (const float*)d_in[9];
    const float* lW2 = (const float*)d_in[10];
    const float* lb2 = (const float*)d_in[11];
    float* out = (float*)d_out;

    int n = in_sizes[0] / 64;   // 50000
    int e = in_sizes[1] / 2;    // 800000
    const int* src = ei;
    const int* dst = ei + e;

    void *p_xwh, *p_H, *p_x16;
    void *p_W1h, *p_W1l, *p_W2h, *p_W2l, *p_W3h, *p_W3l, *p_L1h, *p_L1l;
    cudaGetSymbolAddress(&p_xwh, g_xwh);
    cudaGetSymbolAddress(&p_H,   g_H);
    cudaGetSymbolAddress(&p_x16, g_x16);
    cudaGetSymbolAddress(&p_W1h, g_W1h); cudaGetSymbolAddress(&p_W1l, g_W1l);
    cudaGetSymbolAddress(&p_W2h, g_W2h); cudaGetSymbolAddress(&p_W2l, g_W2l);
    cudaGetSymbolAddress(&p_W3h, g_W3h); cudaGetSymbolAddress(&p_W3l, g_W3l);
    cudaGetSymbolAddress(&p_L1h, g_L1h); cudaGetSymbolAddress(&p_L1l, g_L1l);
    __half* H = (__half*)p_H;

    cudaFuncSetAttribute(mm3<0, 1>, cudaFuncAttributeMaxDynamicSharedMemorySize, SM_TOTAL);
    cudaFuncSetAttribute(mm3<2, 0>, cudaFuncAttributeMaxDynamicSharedMemorySize, SM_TOTAL);

    // one-time side stream + fork/join events (host resources, not device mem)
    static cudaStream_t s2 = nullptr;
    static cudaEvent_t evFork = nullptr, evJoin = nullptr;
    if (!s2) {
        cudaStreamCreateWithFlags(&s2, cudaStreamNonBlocking);
        cudaEventCreateWithFlags(&evFork, cudaEventDisableTiming);
        cudaEventCreateWithFlags(&evJoin, cudaEventDisableTiming);
    }

    int nb = (n + 1023) / 1024;
    int gm = MAXN / 128;               // 392
    int aggBlocks = (n + 7) / 8;

    // ---- fork: CSR branch on s2, convert+conv1 on main ----
    cudaEventRecord(evFork, 0);
    cudaStreamWaitEvent(s2, evFork, 0);

    k_zero<<<(MAXN + 255) / 256, 256, 0, s2>>>(n);
    k_deg<<<(e + 255) / 256, 256, 0, s2>>>(dst, e);

    k_cvt_x<<<(MAXN * 16 + 255) / 256, 256>>>(x, n);
    k_cvt_w<<<(188416 + 255) / 256, 256>>>(W1, W2, W3, lW1);

    k_scan1<<<nb, 1024, 0, s2>>>(n);
    k_scan2<<<1, 64, 0, s2>>>(nb);
    k_scan3<<<nb, 1024, 0, s2>>>(n, e);
    k_fill<<<(e + 255) / 256, 256, 0, s2>>>(src, dst, e);
    cudaEventRecord(evJoin, s2);

    mm3<0, 1><<<dim3(gm, 1), 256, SM_TOTAL>>>((__half*)p_x16, 64,
                                              (__half*)p_W1h, (__half*)p_W1l, 64,
                                              p_xwh, 128, nullptr, nullptr, 64);

    cudaStreamWaitEvent(0, evJoin, 0);

    // conv1 aggregation
    k_agg<<<aggBlocks, 256>>>(b1, 0, n);
    // conv2
    mm3<0, 1><<<dim3(gm, 1), 256, SM_TOTAL>>>(H, 384,
                                              (__half*)p_W2h, (__half*)p_W2l, 128,
                                              p_xwh, 128, nullptr, nullptr, 128);
    k_agg<<<aggBlocks, 256>>>(b2, 128, n);
    // conv3
    mm3<0, 1><<<dim3(gm, 1), 256, SM_TOTAL>>>(H + 128, 384,
                                              (__half*)p_W3h, (__half*)p_W3l, 128,
                                              p_xwh, 128, nullptr, nullptr, 128);
    k_agg<<<aggBlocks, 256>>>(b3, 256, n);

    // MLP fused: partial relu(H@lW1^T+lb1) @ lW2^T accumulated into g_out2
    mm3<2, 0><<<dim3(gm, 3), 256, SM_TOTAL>>>(H, 384,
                                              (__half*)p_L1h, (__half*)p_L1l, 384,
                                              nullptr, 0, lb1, lW2, 384);

    // bias + softmax
    k_final2<<<(n + 255) / 256, 256>>>(lb2, out, n);
}